// round 12
// baseline (speedup 1.0000x reference)
#include <cuda_runtime.h>
#include <cuda_fp16.h>
#include <cstdint>

// Problem constants: B=8, T=2048, S=2048, D=512
#define BB 8
#define TT 2048
#define SN 2048
#define DD 512

typedef uint32_t u32;
typedef uint64_t u64;

// ----------------- device scratch (allocation-free rules) -----------------
__device__ __half g_Qh[(size_t)BB * TT * DD];
__device__ __half g_Ql[(size_t)BB * TT * DD];
__device__ __half g_Ah[(size_t)BB * SN * DD];   // attn_input split (K-major)
__device__ __half g_Al[(size_t)BB * SN * DD];
__device__ __half g_Vt[(size_t)BB * DD * SN];   // attn_input transposed [B][D][S], hi limb
__device__ __half g_Wh[(size_t)DD * DD];
__device__ __half g_Wl[(size_t)DD * DD];
__device__ __half g_Kh[(size_t)BB * SN * DD];
__device__ __half g_Kl[(size_t)BB * SN * DD];
__device__ float g_P[(size_t)BB * TT * SN];     // 128 MB raw scores
__device__ __half g_Ph[(size_t)BB * TT * SN];   // 64 MB softmax probs

// ----------------- helpers -----------------
__device__ __forceinline__ u32 smem_u32(const void* p) {
    u32 a;
    asm("{ .reg .u64 t; cvta.to.shared.u64 t, %1; cvt.u32.u64 %0, t; }" : "=r"(a) : "l"(p));
    return a;
}
// pack two fp32 -> half2 word; first arg = high half, second = low half
__device__ __forceinline__ u32 packh(float hi_elem, float lo_elem) {
    __half2 h = __floats2half2_rn(lo_elem, hi_elem);
    return *(u32*)&h;
}
__device__ __forceinline__ float lo_h2f(u32 p) {
    __half2 h = *(__half2*)&p;
    return __half2float(__low2half(h));
}
__device__ __forceinline__ float hi_h2f(u32 p) {
    __half2 h = *(__half2*)&p;
    return __half2float(__high2half(h));
}

__device__ __forceinline__ void cp16(u32 dst, const void* src) {
    asm volatile("cp.async.cg.shared.global [%0], [%1], 16;" :: "r"(dst), "l"(src));
}
__device__ __forceinline__ void cp_commit() {
    asm volatile("cp.async.commit_group;" ::: "memory");
}
template <int N>
__device__ __forceinline__ void cp_wait() {
    asm volatile("cp.async.wait_group %0;" :: "n"(N) : "memory");
}

__device__ __forceinline__ void ldm_x4(u32* r, u32 addr) {
    asm volatile("ldmatrix.sync.aligned.m8n8.x4.shared.b16 {%0,%1,%2,%3}, [%4];"
                 : "=r"(r[0]), "=r"(r[1]), "=r"(r[2]), "=r"(r[3]) : "r"(addr));
}
__device__ __forceinline__ void mma16816(float* d, const u32* a, const u32* b) {
    asm volatile(
        "mma.sync.aligned.m16n8k16.row.col.f32.f16.f16.f32 "
        "{%0,%1,%2,%3}, {%4,%5,%6,%7}, {%8,%9}, {%0,%1,%2,%3};"
        : "+f"(d[0]), "+f"(d[1]), "+f"(d[2]), "+f"(d[3])
        : "r"(a[0]), "r"(a[1]), "r"(a[2]), "r"(a[3]), "r"(b[0]), "r"(b[1]));
}

// ----------------- GEMM smem layout -----------------
// Tiles: 128 rows x 32 fp16 (64B data), row pitch 80B (conflict-free ldmatrix).
// 2-stage pipeline so two CTAs fit per SM (cross-CTA bubble filling).
#define TPITCH 80
#define TILEB (128 * TPITCH)
#define NSTAGE 2

// =====================================================================
// NT split-fp16 GEMM: C[m][n] = sum_k A[m][k]*B(n,k) (+bias[n])
//   ALIMBS/BLIMBS in {1,2}. Passes: hh [, Ah*Bl] [, Al*Bh], frag loads
//   sequenced per pass to cap register pressure.
//   CTA 128x128, 8 warps (64x32 warp tile), K-chunk 32, 2-stage cp.async,
//   __launch_bounds__(256, 2) -> 2 CTAs/SM.
// =====================================================================
template <int ALIMBS, int BLIMBS, bool WRITE_SPLIT, bool ADD_BIAS>
__global__ void __launch_bounds__(256, 2) gemm_mma(
    const __half* __restrict__ Ah_, const __half* __restrict__ Al_,
    const __half* __restrict__ Bh_, const __half* __restrict__ Bl_,
    const float* __restrict__ bias,
    float* __restrict__ Cf, __half* __restrict__ Ch, __half* __restrict__ Cl,
    int K, int lda, int ldb, int ldc,
    long sA, long sB, long sC)
{
    constexpr int NT = ALIMBS + BLIMBS;
    constexpr int STAGEB = NT * TILEB;
    constexpr int BOFF = ALIMBS * TILEB;

    extern __shared__ char sm[];
    const u32 smb = smem_u32(sm);
    const int tid = threadIdx.x;
    const int wid = tid >> 5, lane = tid & 31;
    const int m0 = blockIdx.y * 128, n0 = blockIdx.x * 128;
    const int bz = blockIdx.z;

    const __half* Arh = Ah_ + (size_t)bz * sA + (size_t)m0 * lda;
    const __half* Arl = (ALIMBS == 2) ? (Al_ + (size_t)bz * sA + (size_t)m0 * lda) : nullptr;
    const __half* Brh = Bh_ + (size_t)bz * sB + (size_t)n0 * ldb;
    const __half* Brl = (BLIMBS == 2) ? (Bl_ + (size_t)bz * sB + (size_t)n0 * ldb) : nullptr;

    // loader: 256 threads, two 16B chunks per tile per thread (rows r, r+64)
    const int lrow = tid >> 2;            // 0..63
    const int lc = (tid & 3) * 16;        // byte offset within 64B k-row

    // warp tile: warp_m in {0,1} (64 rows), warp_n in {0..3} (32 cols)
    const int warp_m = wid >> 2;
    const int warp_n = wid & 3;
    const int a_row = warp_m * 64 + (lane & 15);
    const int a_col = (lane >> 4) * 16;
    const int b_row = warp_n * 32 + ((lane >> 4) << 3) + (lane & 7);
    const int b_col = ((lane >> 3) & 1) * 16;

    float acc[4][4][4];
#pragma unroll
    for (int i = 0; i < 4; i++)
#pragma unroll
        for (int j = 0; j < 4; j++)
#pragma unroll
            for (int q = 0; q < 4; q++) acc[i][j][q] = 0.f;

    const int nch = K >> 5;

#define LOAD_TILE_PAIR(ptr, toff, st, kc_)                                          \
    do {                                                                            \
        cp16(smb + (st) * STAGEB + (toff) + lrow * TPITCH + lc,                     \
             (const char*)((ptr) + (size_t)lrow * ld_ + (kc_)) + lc);               \
        cp16(smb + (st) * STAGEB + (toff) + (lrow + 64) * TPITCH + lc,              \
             (const char*)((ptr) + (size_t)(lrow + 64) * ld_ + (kc_)) + lc);        \
    } while (0)

#define LOAD_CHUNK(cidx, st)                                                        \
    do {                                                                            \
        const int kc_ = (cidx) << 5;                                                \
        { const int ld_ = lda; LOAD_TILE_PAIR(Arh, 0, st, kc_);                     \
          if (ALIMBS == 2) LOAD_TILE_PAIR(Arl, TILEB, st, kc_); }                   \
        { const int ld_ = ldb; LOAD_TILE_PAIR(Brh, BOFF, st, kc_);                  \
          if (BLIMBS == 2) LOAD_TILE_PAIR(Brl, BOFF + TILEB, st, kc_); }            \
        cp_commit();                                                                \
    } while (0)

    LOAD_CHUNK(0, 0);
    LOAD_CHUNK(1, 1);

    for (int c = 0; c < nch; c++) {
        const int st = c & 1;
        cp_wait<1>();
        __syncthreads();

        const u32 sb = smb + st * STAGEB;
#pragma unroll
        for (int ks = 0; ks < 2; ks++) {
            // ---- pass 0: Ah * Bh ----
            u32 ah[4][4], bh[2][4];
#pragma unroll
            for (int mi = 0; mi < 4; mi++)
                ldm_x4(ah[mi], sb + (a_row + mi * 16) * TPITCH + ks * 32 + a_col);
#pragma unroll
            for (int nj2 = 0; nj2 < 2; nj2++)
                ldm_x4(bh[nj2], sb + BOFF + (b_row + nj2 * 16) * TPITCH + ks * 32 + b_col);
#pragma unroll
            for (int mi = 0; mi < 4; mi++)
#pragma unroll
                for (int nj = 0; nj < 4; nj++)
                    mma16816(acc[mi][nj], ah[mi], &bh[nj >> 1][(nj & 1) * 2]);

            if (BLIMBS == 2) {
                // ---- pass 1: Ah * Bl ----
                u32 bl[2][4];
#pragma unroll
                for (int nj2 = 0; nj2 < 2; nj2++)
                    ldm_x4(bl[nj2], sb + BOFF + TILEB + (b_row + nj2 * 16) * TPITCH + ks * 32 + b_col);
#pragma unroll
                for (int mi = 0; mi < 4; mi++)
#pragma unroll
                    for (int nj = 0; nj < 4; nj++)
                        mma16816(acc[mi][nj], ah[mi], &bl[nj >> 1][(nj & 1) * 2]);
            }
            if (ALIMBS == 2) {
                // ---- pass 2: Al * Bh ----
                u32 al[4][4];
#pragma unroll
                for (int mi = 0; mi < 4; mi++)
                    ldm_x4(al[mi], sb + TILEB + (a_row + mi * 16) * TPITCH + ks * 32 + a_col);
#pragma unroll
                for (int mi = 0; mi < 4; mi++)
#pragma unroll
                    for (int nj = 0; nj < 4; nj++)
                        mma16816(acc[mi][nj], al[mi], &bh[nj >> 1][(nj & 1) * 2]);
            }
        }
        __syncthreads();   // all warps done reading stage st
        if (c + 2 < nch) LOAD_CHUNK(c + 2, st);
        else cp_commit();  // keep group numbering uniform
    }
#undef LOAD_CHUNK
#undef LOAD_TILE_PAIR

    // ---- epilogue ----
    const int erow = m0 + warp_m * 64 + (lane >> 2);
    const int ecol0 = n0 + warp_n * 32 + (lane & 3) * 2;
#pragma unroll
    for (int mi = 0; mi < 4; mi++) {
#pragma unroll
        for (int nj = 0; nj < 4; nj++) {
            float v0 = acc[mi][nj][0], v1 = acc[mi][nj][1];
            float v2 = acc[mi][nj][2], v3 = acc[mi][nj][3];
            const int col = ecol0 + nj * 8;
            if (ADD_BIAS) {
                float b0 = bias[col], b1 = bias[col + 1];
                v0 += b0; v1 += b1; v2 += b0; v3 += b1;
            }
            const size_t r0 = (size_t)bz * sC + (size_t)(erow + mi * 16) * ldc + col;
            const size_t r1 = r0 + (size_t)8 * ldc;
            if (!WRITE_SPLIT) {
                *(float2*)(Cf + r0) = make_float2(v0, v1);
                *(float2*)(Cf + r1) = make_float2(v2, v3);
            } else {
                u32 h0 = packh(v1, v0);
                u32 l0 = packh(v1 - hi_h2f(h0), v0 - lo_h2f(h0));
                u32 h1 = packh(v3, v2);
                u32 l1 = packh(v3 - hi_h2f(h1), v2 - lo_h2f(h1));
                *(u32*)(Ch + r0) = h0; *(u32*)(Cl + r0) = l0;
                *(u32*)(Ch + r1) = h1; *(u32*)(Cl + r1) = l1;
            }
        }
    }
}

// =====================================================================
// fp32 -> (hi, lo) fp16 split converter (Q, W)
// =====================================================================
__global__ void __launch_bounds__(256) convert_split(
    const float* __restrict__ x, __half* __restrict__ h,
    __half* __restrict__ l, int n4)
{
    int i = blockIdx.x * 256 + threadIdx.x;
    if (i >= n4) return;
    float4 v = ((const float4*)x)[i];
    u32 h0 = packh(v.y, v.x);
    u32 h1 = packh(v.w, v.z);
    u32 l0 = packh(v.y - hi_h2f(h0), v.x - lo_h2f(h0));
    u32 l1 = packh(v.w - hi_h2f(h1), v.z - lo_h2f(h1));
    ((uint2*)h)[i] = make_uint2(h0, h1);
    ((uint2*)l)[i] = make_uint2(l0, l1);
}

// =====================================================================
// Fused attn_input prep: split (Ah, Al) K-major + transpose (Vt) in one read
// =====================================================================
__global__ void __launch_bounds__(256) fuse_attn(
    const float* __restrict__ x, __half* __restrict__ ah,
    __half* __restrict__ al, __half* __restrict__ vt)
{
    __shared__ float tile[32][33];
    const int tx = threadIdx.x & 31, ty = threadIdx.x >> 5;  // 32x8
    const int s0 = blockIdx.x * 32, d0 = blockIdx.y * 32, b = blockIdx.z;
    const float* src = x + (size_t)b * SN * DD;
#pragma unroll
    for (int j = 0; j < 4; j++) {
        int s = s0 + ty + j * 8;
        float v = src[(size_t)s * DD + d0 + tx];
        tile[ty + j * 8][tx] = v;
        __half h = __float2half_rn(v);
        size_t off = (size_t)b * SN * DD + (size_t)s * DD + d0 + tx;
        ah[off] = h;
        al[off] = __float2half_rn(v - __half2float(h));
    }
    __syncthreads();
#pragma unroll
    for (int j = 0; j < 4; j++) {
        int d = d0 + ty + j * 8;
        int s = s0 + tx;
        vt[(size_t)b * DD * SN + (size_t)d * SN + s] = __float2half_rn(tile[tx][ty + j * 8]);
    }
}

// =====================================================================
// Row softmax over S=2048 (fp32 in), writing fp16 P (hi limb only)
// =====================================================================
__global__ void __launch_bounds__(256) softmax_half(
    const float* __restrict__ P, __half* __restrict__ Ph)
{
    __shared__ float red[8];
    const int tid = threadIdx.x;
    const int lane = tid & 31, warp = tid >> 5;
    const float* row = P + (size_t)blockIdx.x * SN;

    float4 v0 = ((const float4*)row)[tid];
    float4 v1 = ((const float4*)row)[tid + 256];

    float m = fmaxf(fmaxf(fmaxf(v0.x, v0.y), fmaxf(v0.z, v0.w)),
                    fmaxf(fmaxf(v1.x, v1.y), fmaxf(v1.z, v1.w)));
#pragma unroll
    for (int o = 16; o > 0; o >>= 1) m = fmaxf(m, __shfl_xor_sync(0xffffffffu, m, o));
    if (lane == 0) red[warp] = m;
    __syncthreads();
    float mall = red[0];
#pragma unroll
    for (int k = 1; k < 8; k++) mall = fmaxf(mall, red[k]);
    __syncthreads();

    v0.x = __expf(v0.x - mall); v0.y = __expf(v0.y - mall);
    v0.z = __expf(v0.z - mall); v0.w = __expf(v0.w - mall);
    v1.x = __expf(v1.x - mall); v1.y = __expf(v1.y - mall);
    v1.z = __expf(v1.z - mall); v1.w = __expf(v1.w - mall);

    float s = (v0.x + v0.y) + (v0.z + v0.w) + (v1.x + v1.y) + (v1.z + v1.w);
#pragma unroll
    for (int o = 16; o > 0; o >>= 1) s += __shfl_xor_sync(0xffffffffu, s, o);
    if (lane == 0) red[warp] = s;
    __syncthreads();
    float sall = red[0];
#pragma unroll
    for (int k = 1; k < 8; k++) sall += red[k];
    float inv = 1.0f / sall;

    v0.x *= inv; v0.y *= inv; v0.z *= inv; v0.w *= inv;
    v1.x *= inv; v1.y *= inv; v1.z *= inv; v1.w *= inv;

    uint2* ph2 = (uint2*)(Ph + (size_t)blockIdx.x * SN);
    ph2[tid]       = make_uint2(packh(v0.y, v0.x), packh(v0.w, v0.z));
    ph2[tid + 256] = make_uint2(packh(v1.y, v1.x), packh(v1.w, v1.z));
}

// =====================================================================
// kernel_launch
// =====================================================================
extern "C" void kernel_launch(void* const* d_in, const int* in_sizes, int n_in,
                              void* d_out, int out_size) {
    const float* main_in = (const float*)d_in[0];
    const float* attn_in = (const float*)d_in[1];
    const float* W_f = (const float*)d_in[2];
    const float* b_f = (const float*)d_in[3];
    float* out = (float*)d_out;

    __half *Qh, *Ql, *Ah, *Al, *Vt, *Wh, *Wl, *Kh, *Kl, *Ph;
    float* P;
    cudaGetSymbolAddress((void**)&Qh, g_Qh);  cudaGetSymbolAddress((void**)&Ql, g_Ql);
    cudaGetSymbolAddress((void**)&Ah, g_Ah);  cudaGetSymbolAddress((void**)&Al, g_Al);
    cudaGetSymbolAddress((void**)&Vt, g_Vt);
    cudaGetSymbolAddress((void**)&Wh, g_Wh);  cudaGetSymbolAddress((void**)&Wl, g_Wl);
    cudaGetSymbolAddress((void**)&Kh, g_Kh);  cudaGetSymbolAddress((void**)&Kl, g_Kl);
    cudaGetSymbolAddress((void**)&Ph, g_Ph);
    cudaGetSymbolAddress((void**)&P, g_P);

    // 0) input prep (attn_input read once: split + transpose fused)
    {
        int n4q = (BB * TT * DD) / 4;
        convert_split<<<n4q / 256, 256>>>(main_in, Qh, Ql, n4q);
        int n4w = (DD * DD) / 4;
        convert_split<<<(n4w + 255) / 256, 256>>>(W_f, Wh, Wl, n4w);
        dim3 fg(SN / 32, DD / 32, BB);
        fuse_attn<<<fg, 256>>>(attn_in, Ah, Al, Vt);
    }

    constexpr int SMEM22 = NSTAGE * 4 * TILEB;  // 81920  (2 CTAs/SM: 160KB)
    constexpr int SMEM11 = NSTAGE * 2 * TILEB;  // 40960
    cudaFuncSetAttribute(gemm_mma<2, 2, true, true>,
                         cudaFuncAttributeMaxDynamicSharedMemorySize, SMEM22);
    cudaFuncSetAttribute(gemm_mma<2, 2, false, false>,
                         cudaFuncAttributeMaxDynamicSharedMemorySize, SMEM22);
    cudaFuncSetAttribute(gemm_mma<1, 1, false, false>,
                         cudaFuncAttributeMaxDynamicSharedMemorySize, SMEM11);

    // 1) keys = attn @ W^T + b -> split fp16 (Kh + Kl). 3 passes.
    {
        dim3 grid(DD / 128, (BB * SN) / 128, 1);
        gemm_mma<2, 2, true, true><<<grid, 256, SMEM22>>>(
            Ah, Al, Wh, Wl, b_f, nullptr, Kh, Kl,
            DD, DD, DD, DD, 0, 0, 0);
    }

    // 2) scores = (Qh+Ql) @ (Kh+Kl)^T -> fp32 P. 3 passes.
    {
        dim3 grid(SN / 128, TT / 128, BB);
        gemm_mma<2, 2, false, false><<<grid, 256, SMEM22>>>(
            Qh, Ql, Kh, Kl, nullptr, P, nullptr, nullptr,
            DD, DD, DD, SN,
            (long)TT * DD, (long)SN * DD, (long)TT * SN);
    }

    // 3) softmax -> fp16 Ph
    softmax_half<<<BB * TT, 256>>>(P, Ph);

    // 4) out = Ph @ Vt. single pass.
    {
        dim3 grid(DD / 128, TT / 128, BB);
        gemm_mma<1, 1, false, false><<<grid, 256, SMEM11>>>(
            Ph, nullptr, Vt, nullptr, nullptr, out, nullptr, nullptr,
            SN, SN, SN, DD,
            (long)TT * SN, (long)DD * SN, (long)TT * DD);
    }
}

// round 13
// speedup vs baseline: 1.2813x; 1.2813x over previous
#include <cuda_runtime.h>
#include <cuda_fp16.h>
#include <cstdint>

// Problem constants: B=8, T=2048, S=2048, D=512
#define BB 8
#define TT 2048
#define SN 2048
#define DD 512

typedef uint32_t u32;
typedef uint64_t u64;

// ----------------- device scratch (allocation-free rules) -----------------
__device__ __half g_Qh[(size_t)BB * TT * DD];
__device__ __half g_Ql[(size_t)BB * TT * DD];
__device__ __half g_Ah[(size_t)BB * SN * DD];   // attn_input split (K-major)
__device__ __half g_Al[(size_t)BB * SN * DD];
__device__ __half g_Vt[(size_t)BB * DD * SN];   // attn_input transposed [B][D][S], hi limb
__device__ __half g_Wh[(size_t)DD * DD];
__device__ __half g_Wl[(size_t)DD * DD];
__device__ __half g_Kh[(size_t)BB * SN * DD];
__device__ __half g_Kl[(size_t)BB * SN * DD];
__device__ float g_P[(size_t)BB * TT * SN];     // 128 MB raw scores
__device__ __half g_Ph[(size_t)BB * TT * SN];   // 64 MB softmax probs

// ----------------- helpers -----------------
__device__ __forceinline__ u32 smem_u32(const void* p) {
    u32 a;
    asm("{ .reg .u64 t; cvta.to.shared.u64 t, %1; cvt.u32.u64 %0, t; }" : "=r"(a) : "l"(p));
    return a;
}
// pack two fp32 -> half2 word; first arg = high half, second = low half
__device__ __forceinline__ u32 packh(float hi_elem, float lo_elem) {
    __half2 h = __floats2half2_rn(lo_elem, hi_elem);
    return *(u32*)&h;
}
__device__ __forceinline__ float lo_h2f(u32 p) {
    __half2 h = *(__half2*)&p;
    return __half2float(__low2half(h));
}
__device__ __forceinline__ float hi_h2f(u32 p) {
    __half2 h = *(__half2*)&p;
    return __half2float(__high2half(h));
}

__device__ __forceinline__ void cp16(u32 dst, const void* src) {
    asm volatile("cp.async.cg.shared.global [%0], [%1], 16;" :: "r"(dst), "l"(src));
}
__device__ __forceinline__ void cp_commit() {
    asm volatile("cp.async.commit_group;" ::: "memory");
}
template <int N>
__device__ __forceinline__ void cp_wait() {
    asm volatile("cp.async.wait_group %0;" :: "n"(N) : "memory");
}

__device__ __forceinline__ void ldm_x4(u32* r, u32 addr) {
    asm volatile("ldmatrix.sync.aligned.m8n8.x4.shared.b16 {%0,%1,%2,%3}, [%4];"
                 : "=r"(r[0]), "=r"(r[1]), "=r"(r[2]), "=r"(r[3]) : "r"(addr));
}
__device__ __forceinline__ void mma16816(float* d, const u32* a, const u32* b) {
    asm volatile(
        "mma.sync.aligned.m16n8k16.row.col.f32.f16.f16.f32 "
        "{%0,%1,%2,%3}, {%4,%5,%6,%7}, {%8,%9}, {%0,%1,%2,%3};"
        : "+f"(d[0]), "+f"(d[1]), "+f"(d[2]), "+f"(d[3])
        : "r"(a[0]), "r"(a[1]), "r"(a[2]), "r"(a[3]), "r"(b[0]), "r"(b[1]));
}

// ----------------- GEMM smem layout -----------------
// Tiles: 128 rows x 64 fp16 (128B data), row pitch 144B.
// 144B = 36 words stride: 8 consecutive rows hit bank groups 4i mod 32 -> all
// distinct, conflict-free ldmatrix. K-chunk 64 halves barrier count vs 32.
#define TPITCH 144
#define TILEB (128 * TPITCH)
#define NSTAGE 3

// =====================================================================
// NT split-fp16 GEMM: C[m][n] = sum_k A[m][k]*B(n,k) (+bias[n])
//   ALIMBS/BLIMBS in {1,2}. Passes (pass-major): hh [, Ah*Bl] [, Al*Bh].
//   WRITE_SPLIT: write hi/lo fp16 limb pair instead of fp32.
//   CTA 128x128, 16 warps (32x32 warp tile), K-chunk 64, 3-stage cp.async.
// =====================================================================
template <int ALIMBS, int BLIMBS, bool WRITE_SPLIT, bool ADD_BIAS>
__global__ void __launch_bounds__(512, 1) gemm_mma(
    const __half* __restrict__ Ah_, const __half* __restrict__ Al_,
    const __half* __restrict__ Bh_, const __half* __restrict__ Bl_,
    const float* __restrict__ bias,
    float* __restrict__ Cf, __half* __restrict__ Ch, __half* __restrict__ Cl,
    int K, int lda, int ldb, int ldc,
    long sA, long sB, long sC)
{
    constexpr int NT = ALIMBS + BLIMBS;
    constexpr int STAGEB = NT * TILEB;
    constexpr int BOFF = ALIMBS * TILEB;

    extern __shared__ char sm[];
    const u32 smb = smem_u32(sm);
    const int tid = threadIdx.x;
    const int wid = tid >> 5, lane = tid & 31;
    const int m0 = blockIdx.y * 128, n0 = blockIdx.x * 128;
    const int bz = blockIdx.z;

    const __half* Arh = Ah_ + (size_t)bz * sA + (size_t)m0 * lda;
    const __half* Arl = (ALIMBS == 2) ? (Al_ + (size_t)bz * sA + (size_t)m0 * lda) : nullptr;
    const __half* Brh = Bh_ + (size_t)bz * sB + (size_t)n0 * ldb;
    const __half* Brl = (BLIMBS == 2) ? (Bl_ + (size_t)bz * sB + (size_t)n0 * ldb) : nullptr;

    // loader: 512 threads; per tile each thread covers row lrow, 2 x 16B at
    // byte cols lc and lc+64 (row = 128 data bytes).
    const int lrow = tid >> 2;            // 0..127
    const int lc = (tid & 3) * 16;        // 0,16,32,48

    // warp tile: warp_m in {0..3} (32 rows), warp_n in {0..3} (32 cols)
    const int warp_m = wid >> 2;
    const int warp_n = wid & 3;
    const int a_row = warp_m * 32 + (lane & 15);
    const int a_col = (lane >> 4) * 16;
    const int b_row = warp_n * 32 + ((lane >> 4) << 3) + (lane & 7);
    const int b_col = ((lane >> 3) & 1) * 16;

    float acc[2][4][4];
#pragma unroll
    for (int i = 0; i < 2; i++)
#pragma unroll
        for (int j = 0; j < 4; j++)
#pragma unroll
            for (int q = 0; q < 4; q++) acc[i][j][q] = 0.f;

    const int nch = K >> 6;               // K-chunk 64

#define LOAD_TILE(ptr, toff, st, kc_, ld_)                                          \
    do {                                                                            \
        cp16(smb + (st) * STAGEB + (toff) + lrow * TPITCH + lc,                     \
             (const char*)((ptr) + (size_t)lrow * (ld_) + (kc_)) + lc);             \
        cp16(smb + (st) * STAGEB + (toff) + lrow * TPITCH + lc + 64,                \
             (const char*)((ptr) + (size_t)lrow * (ld_) + (kc_)) + lc + 64);        \
    } while (0)

#define LOAD_CHUNK(cidx, st)                                                        \
    do {                                                                            \
        const int kc_ = (cidx) << 6;                                                \
        LOAD_TILE(Arh, 0, st, kc_, lda);                                            \
        if (ALIMBS == 2) LOAD_TILE(Arl, TILEB, st, kc_, lda);                       \
        LOAD_TILE(Brh, BOFF, st, kc_, ldb);                                         \
        if (BLIMBS == 2) LOAD_TILE(Brl, BOFF + TILEB, st, kc_, ldb);                \
        cp_commit();                                                                \
    } while (0)

    LOAD_CHUNK(0, 0);
    LOAD_CHUNK(1, 1);

    int st = 0, st_load = 2;
    for (int c = 0; c < nch; c++) {
        cp_wait<1>();
        __syncthreads();

        if (c + 2 < nch) {
            LOAD_CHUNK(c + 2, st_load);
            if (++st_load == NSTAGE) st_load = 0;
        } else {
            cp_commit();  // keep group numbering uniform
        }

        const u32 sb = smb + st * STAGEB;
#pragma unroll
        for (int ks = 0; ks < 4; ks++) {
            u32 ah[2][4], al[2][4], bh[2][4], bl[2][4];
#pragma unroll
            for (int mi = 0; mi < 2; mi++) {
                u32 addr = sb + (a_row + mi * 16) * TPITCH + ks * 32 + a_col;
                ldm_x4(ah[mi], addr);
                if (ALIMBS == 2) ldm_x4(al[mi], addr + TILEB);
            }
#pragma unroll
            for (int nj2 = 0; nj2 < 2; nj2++) {
                u32 addr = sb + BOFF + (b_row + nj2 * 16) * TPITCH + ks * 32 + b_col;
                ldm_x4(bh[nj2], addr);
                if (BLIMBS == 2) ldm_x4(bl[nj2], addr + TILEB);
            }

            // pass 0: Ah * Bh
#pragma unroll
            for (int mi = 0; mi < 2; mi++)
#pragma unroll
                for (int nj = 0; nj < 4; nj++)
                    mma16816(acc[mi][nj], ah[mi], &bh[nj >> 1][(nj & 1) * 2]);
            if (BLIMBS == 2) {
                // pass 1: Ah * Bl
#pragma unroll
                for (int mi = 0; mi < 2; mi++)
#pragma unroll
                    for (int nj = 0; nj < 4; nj++)
                        mma16816(acc[mi][nj], ah[mi], &bl[nj >> 1][(nj & 1) * 2]);
            }
            if (ALIMBS == 2) {
                // pass 2: Al * Bh
#pragma unroll
                for (int mi = 0; mi < 2; mi++)
#pragma unroll
                    for (int nj = 0; nj < 4; nj++)
                        mma16816(acc[mi][nj], al[mi], &bh[nj >> 1][(nj & 1) * 2]);
            }
        }
        if (++st == NSTAGE) st = 0;
    }
#undef LOAD_CHUNK
#undef LOAD_TILE

    const int erow = m0 + warp_m * 32 + (lane >> 2);
    const int ecol0 = n0 + warp_n * 32 + (lane & 3) * 2;
#pragma unroll
    for (int mi = 0; mi < 2; mi++) {
#pragma unroll
        for (int nj = 0; nj < 4; nj++) {
            float v0 = acc[mi][nj][0], v1 = acc[mi][nj][1];
            float v2 = acc[mi][nj][2], v3 = acc[mi][nj][3];
            const int col = ecol0 + nj * 8;
            if (ADD_BIAS) {
                float b0 = bias[col], b1 = bias[col + 1];
                v0 += b0; v1 += b1; v2 += b0; v3 += b1;
            }
            const size_t r0 = (size_t)bz * sC + (size_t)(erow + mi * 16) * ldc + col;
            const size_t r1 = r0 + (size_t)8 * ldc;
            if (!WRITE_SPLIT) {
                *(float2*)(Cf + r0) = make_float2(v0, v1);
                *(float2*)(Cf + r1) = make_float2(v2, v3);
            } else {
                u32 h0 = packh(v1, v0);
                u32 l0 = packh(v1 - hi_h2f(h0), v0 - lo_h2f(h0));
                u32 h1 = packh(v3, v2);
                u32 l1 = packh(v3 - hi_h2f(h1), v2 - lo_h2f(h1));
                *(u32*)(Ch + r0) = h0; *(u32*)(Cl + r0) = l0;
                *(u32*)(Ch + r1) = h1; *(u32*)(Cl + r1) = l1;
            }
        }
    }
}

// =====================================================================
// fp32 -> (hi, lo) fp16 split converter (Q, W)
// =====================================================================
__global__ void __launch_bounds__(256) convert_split(
    const float* __restrict__ x, __half* __restrict__ h,
    __half* __restrict__ l, int n4)
{
    int i = blockIdx.x * 256 + threadIdx.x;
    if (i >= n4) return;
    float4 v = ((const float4*)x)[i];
    u32 h0 = packh(v.y, v.x);
    u32 h1 = packh(v.w, v.z);
    u32 l0 = packh(v.y - hi_h2f(h0), v.x - lo_h2f(h0));
    u32 l1 = packh(v.w - hi_h2f(h1), v.z - lo_h2f(h1));
    ((uint2*)h)[i] = make_uint2(h0, h1);
    ((uint2*)l)[i] = make_uint2(l0, l1);
}

// =====================================================================
// Fused attn_input prep: split (Ah, Al) K-major + transpose (Vt) in one read
// =====================================================================
__global__ void __launch_bounds__(256) fuse_attn(
    const float* __restrict__ x, __half* __restrict__ ah,
    __half* __restrict__ al, __half* __restrict__ vt)
{
    __shared__ float tile[32][33];
    const int tx = threadIdx.x & 31, ty = threadIdx.x >> 5;  // 32x8
    const int s0 = blockIdx.x * 32, d0 = blockIdx.y * 32, b = blockIdx.z;
    const float* src = x + (size_t)b * SN * DD;
#pragma unroll
    for (int j = 0; j < 4; j++) {
        int s = s0 + ty + j * 8;
        float v = src[(size_t)s * DD + d0 + tx];
        tile[ty + j * 8][tx] = v;
        __half h = __float2half_rn(v);
        size_t off = (size_t)b * SN * DD + (size_t)s * DD + d0 + tx;
        ah[off] = h;
        al[off] = __float2half_rn(v - __half2float(h));
    }
    __syncthreads();
#pragma unroll
    for (int j = 0; j < 4; j++) {
        int d = d0 + ty + j * 8;
        int s = s0 + tx;
        vt[(size_t)b * DD * SN + (size_t)d * SN + s] = __float2half_rn(tile[tx][ty + j * 8]);
    }
}

// =====================================================================
// Row softmax over S=2048 (fp32 in), writing fp16 P (hi limb only)
// =====================================================================
__global__ void __launch_bounds__(256) softmax_half(
    const float* __restrict__ P, __half* __restrict__ Ph)
{
    __shared__ float red[8];
    const int tid = threadIdx.x;
    const int lane = tid & 31, warp = tid >> 5;
    const float* row = P + (size_t)blockIdx.x * SN;

    float4 v0 = ((const float4*)row)[tid];
    float4 v1 = ((const float4*)row)[tid + 256];

    float m = fmaxf(fmaxf(fmaxf(v0.x, v0.y), fmaxf(v0.z, v0.w)),
                    fmaxf(fmaxf(v1.x, v1.y), fmaxf(v1.z, v1.w)));
#pragma unroll
    for (int o = 16; o > 0; o >>= 1) m = fmaxf(m, __shfl_xor_sync(0xffffffffu, m, o));
    if (lane == 0) red[warp] = m;
    __syncthreads();
    float mall = red[0];
#pragma unroll
    for (int k = 1; k < 8; k++) mall = fmaxf(mall, red[k]);
    __syncthreads();

    v0.x = __expf(v0.x - mall); v0.y = __expf(v0.y - mall);
    v0.z = __expf(v0.z - mall); v0.w = __expf(v0.w - mall);
    v1.x = __expf(v1.x - mall); v1.y = __expf(v1.y - mall);
    v1.z = __expf(v1.z - mall); v1.w = __expf(v1.w - mall);

    float s = (v0.x + v0.y) + (v0.z + v0.w) + (v1.x + v1.y) + (v1.z + v1.w);
#pragma unroll
    for (int o = 16; o > 0; o >>= 1) s += __shfl_xor_sync(0xffffffffu, s, o);
    if (lane == 0) red[warp] = s;
    __syncthreads();
    float sall = red[0];
#pragma unroll
    for (int k = 1; k < 8; k++) sall += red[k];
    float inv = 1.0f / sall;

    v0.x *= inv; v0.y *= inv; v0.z *= inv; v0.w *= inv;
    v1.x *= inv; v1.y *= inv; v1.z *= inv; v1.w *= inv;

    uint2* ph2 = (uint2*)(Ph + (size_t)blockIdx.x * SN);
    ph2[tid]       = make_uint2(packh(v0.y, v0.x), packh(v0.w, v0.z));
    ph2[tid + 256] = make_uint2(packh(v1.y, v1.x), packh(v1.w, v1.z));
}

// =====================================================================
// kernel_launch
// =====================================================================
extern "C" void kernel_launch(void* const* d_in, const int* in_sizes, int n_in,
                              void* d_out, int out_size) {
    const float* main_in = (const float*)d_in[0];
    const float* attn_in = (const float*)d_in[1];
    const float* W_f = (const float*)d_in[2];
    const float* b_f = (const float*)d_in[3];
    float* out = (float*)d_out;

    __half *Qh, *Ql, *Ah, *Al, *Vt, *Wh, *Wl, *Kh, *Kl, *Ph;
    float* P;
    cudaGetSymbolAddress((void**)&Qh, g_Qh);  cudaGetSymbolAddress((void**)&Ql, g_Ql);
    cudaGetSymbolAddress((void**)&Ah, g_Ah);  cudaGetSymbolAddress((void**)&Al, g_Al);
    cudaGetSymbolAddress((void**)&Vt, g_Vt);
    cudaGetSymbolAddress((void**)&Wh, g_Wh);  cudaGetSymbolAddress((void**)&Wl, g_Wl);
    cudaGetSymbolAddress((void**)&Kh, g_Kh);  cudaGetSymbolAddress((void**)&Kl, g_Kl);
    cudaGetSymbolAddress((void**)&Ph, g_Ph);
    cudaGetSymbolAddress((void**)&P, g_P);

    // 0) input prep (attn_input read once: split + transpose fused)
    {
        int n4q = (BB * TT * DD) / 4;
        convert_split<<<n4q / 256, 256>>>(main_in, Qh, Ql, n4q);
        int n4w = (DD * DD) / 4;
        convert_split<<<(n4w + 255) / 256, 256>>>(W_f, Wh, Wl, n4w);
        dim3 fg(SN / 32, DD / 32, BB);
        fuse_attn<<<fg, 256>>>(attn_in, Ah, Al, Vt);
    }

    constexpr int SMEM22 = NSTAGE * 4 * TILEB;  // 221184
    constexpr int SMEM11 = NSTAGE * 2 * TILEB;  // 110592
    cudaFuncSetAttribute(gemm_mma<2, 2, true, true>,
                         cudaFuncAttributeMaxDynamicSharedMemorySize, SMEM22);
    cudaFuncSetAttribute(gemm_mma<2, 2, false, false>,
                         cudaFuncAttributeMaxDynamicSharedMemorySize, SMEM22);
    cudaFuncSetAttribute(gemm_mma<1, 1, false, false>,
                         cudaFuncAttributeMaxDynamicSharedMemorySize, SMEM11);

    // 1) keys = attn @ W^T + b -> split fp16 (Kh + Kl). 3 passes.
    {
        dim3 grid(DD / 128, (BB * SN) / 128, 1);
        gemm_mma<2, 2, true, true><<<grid, 512, SMEM22>>>(
            Ah, Al, Wh, Wl, b_f, nullptr, Kh, Kl,
            DD, DD, DD, DD, 0, 0, 0);
    }

    // 2) scores = (Qh+Ql) @ (Kh+Kl)^T -> fp32 P. 3 passes.
    {
        dim3 grid(SN / 128, TT / 128, BB);
        gemm_mma<2, 2, false, false><<<grid, 512, SMEM22>>>(
            Qh, Ql, Kh, Kl, nullptr, P, nullptr, nullptr,
            DD, DD, DD, SN,
            (long)TT * DD, (long)SN * DD, (long)TT * SN);
    }

    // 3) softmax -> fp16 Ph
    softmax_half<<<BB * TT, 256>>>(P, Ph);

    // 4) out = Ph @ Vt. single pass.
    {
        dim3 grid(DD / 128, TT / 128, BB);
        gemm_mma<1, 1, false, false><<<grid, 512, SMEM11>>>(
            Ph, nullptr, Vt, nullptr, nullptr, out, nullptr, nullptr,
            SN, SN, SN, DD,
            (long)TT * SN, (long)DD * SN, (long)TT * DD);
    }
}

// round 14
// speedup vs baseline: 1.3771x; 1.0747x over previous
#include <cuda_runtime.h>
#include <cuda_fp16.h>
#include <cstdint>

// Problem constants: B=8, T=2048, S=2048, D=512
#define BB 8
#define TT 2048
#define SN 2048
#define DD 512

typedef uint32_t u32;
typedef uint64_t u64;

// ----------------- device scratch (allocation-free rules) -----------------
__device__ __half g_Qh[(size_t)BB * TT * DD];
__device__ __half g_Ql[(size_t)BB * TT * DD];
__device__ __half g_Ah[(size_t)BB * SN * DD];   // attn_input split (K-major)
__device__ __half g_Al[(size_t)BB * SN * DD];
__device__ __half g_Vt[(size_t)BB * DD * SN];   // attn_input transposed [B][D][S], hi limb
__device__ __half g_Wh[(size_t)DD * DD];
__device__ __half g_Wl[(size_t)DD * DD];
__device__ __half g_Kh[(size_t)BB * SN * DD];
__device__ __half g_Kl[(size_t)BB * SN * DD];
__device__ float g_P[(size_t)BB * TT * SN];     // 128 MB raw scores
__device__ __half g_Ph[(size_t)BB * TT * SN];   // 64 MB softmax probs

// ----------------- helpers -----------------
__device__ __forceinline__ u32 smem_u32(const void* p) {
    u32 a;
    asm("{ .reg .u64 t; cvta.to.shared.u64 t, %1; cvt.u32.u64 %0, t; }" : "=r"(a) : "l"(p));
    return a;
}
// pack two fp32 -> half2 word; first arg = high half, second = low half
__device__ __forceinline__ u32 packh(float hi_elem, float lo_elem) {
    __half2 h = __floats2half2_rn(lo_elem, hi_elem);
    return *(u32*)&h;
}
__device__ __forceinline__ float lo_h2f(u32 p) {
    __half2 h = *(__half2*)&p;
    return __half2float(__low2half(h));
}
__device__ __forceinline__ float hi_h2f(u32 p) {
    __half2 h = *(__half2*)&p;
    return __half2float(__high2half(h));
}

__device__ __forceinline__ void cp16(u32 dst, const void* src) {
    asm volatile("cp.async.cg.shared.global [%0], [%1], 16;" :: "r"(dst), "l"(src));
}
__device__ __forceinline__ void cp_commit() {
    asm volatile("cp.async.commit_group;" ::: "memory");
}
template <int N>
__device__ __forceinline__ void cp_wait() {
    asm volatile("cp.async.wait_group %0;" :: "n"(N) : "memory");
}

__device__ __forceinline__ void ldm_x4(u32* r, u32 addr) {
    asm volatile("ldmatrix.sync.aligned.m8n8.x4.shared.b16 {%0,%1,%2,%3}, [%4];"
                 : "=r"(r[0]), "=r"(r[1]), "=r"(r[2]), "=r"(r[3]) : "r"(addr));
}
__device__ __forceinline__ void mma16816(float* d, const u32* a, const u32* b) {
    asm volatile(
        "mma.sync.aligned.m16n8k16.row.col.f32.f16.f16.f32 "
        "{%0,%1,%2,%3}, {%4,%5,%6,%7}, {%8,%9}, {%0,%1,%2,%3};"
        : "+f"(d[0]), "+f"(d[1]), "+f"(d[2]), "+f"(d[3])
        : "r"(a[0]), "r"(a[1]), "r"(a[2]), "r"(a[3]), "r"(b[0]), "r"(b[1]));
}

// ----------------- GEMM smem layout -----------------
// Tiles: rows x 32 fp16 (64B data), row pitch 80B (conflict-free ldmatrix).
#define TPITCH 80
#define TILEA (128 * TPITCH)
#define NSTAGE 3

// =====================================================================
// NT split-fp16 GEMM, R11 version (CTA 128x128, 16 warps, 32x32 warp tile)
// =====================================================================
template <int ALIMBS, int BLIMBS, bool WRITE_SPLIT, bool ADD_BIAS>
__global__ void __launch_bounds__(512, 1) gemm_mma(
    const __half* __restrict__ Ah_, const __half* __restrict__ Al_,
    const __half* __restrict__ Bh_, const __half* __restrict__ Bl_,
    const float* __restrict__ bias,
    float* __restrict__ Cf, __half* __restrict__ Ch, __half* __restrict__ Cl,
    int K, int lda, int ldb, int ldc,
    long sA, long sB, long sC)
{
    constexpr int NT = ALIMBS + BLIMBS;
    constexpr int STAGEB = NT * TILEA;
    constexpr int BOFF = ALIMBS * TILEA;

    extern __shared__ char sm[];
    const u32 smb = smem_u32(sm);
    const int tid = threadIdx.x;
    const int wid = tid >> 5, lane = tid & 31;
    const int m0 = blockIdx.y * 128, n0 = blockIdx.x * 128;
    const int bz = blockIdx.z;

    const __half* Arh = Ah_ + (size_t)bz * sA + (size_t)m0 * lda;
    const __half* Arl = (ALIMBS == 2) ? (Al_ + (size_t)bz * sA + (size_t)m0 * lda) : nullptr;
    const __half* Brh = Bh_ + (size_t)bz * sB + (size_t)n0 * ldb;
    const __half* Brl = (BLIMBS == 2) ? (Bl_ + (size_t)bz * sB + (size_t)n0 * ldb) : nullptr;

    const int lrow = tid >> 2;
    const int lc = (tid & 3) * 16;

    const int warp_m = wid >> 2;
    const int warp_n = wid & 3;
    const int a_row = warp_m * 32 + (lane & 15);
    const int a_col = (lane >> 4) * 16;
    const int b_row = warp_n * 32 + ((lane >> 4) << 3) + (lane & 7);
    const int b_col = ((lane >> 3) & 1) * 16;

    float acc[2][4][4];
#pragma unroll
    for (int i = 0; i < 2; i++)
#pragma unroll
        for (int j = 0; j < 4; j++)
#pragma unroll
            for (int q = 0; q < 4; q++) acc[i][j][q] = 0.f;

    const int nch = K >> 5;

#define LOAD_CHUNK(cidx, st)                                                       \
    do {                                                                           \
        const int kc_ = (cidx) << 5;                                               \
        const u32 sb_ = smb + (st) * STAGEB;                                       \
        cp16(sb_ + 0 * TILEA + lrow * TPITCH + lc,                                 \
             (const char*)(Arh + (size_t)lrow * lda + kc_) + lc);                  \
        if (ALIMBS == 2)                                                           \
            cp16(sb_ + 1 * TILEA + lrow * TPITCH + lc,                             \
                 (const char*)(Arl + (size_t)lrow * lda + kc_) + lc);              \
        cp16(sb_ + BOFF + lrow * TPITCH + lc,                                      \
             (const char*)(Brh + (size_t)lrow * ldb + kc_) + lc);                  \
        if (BLIMBS == 2)                                                           \
            cp16(sb_ + BOFF + TILEA + lrow * TPITCH + lc,                          \
                 (const char*)(Brl + (size_t)lrow * ldb + kc_) + lc);              \
        cp_commit();                                                               \
    } while (0)

    LOAD_CHUNK(0, 0);
    LOAD_CHUNK(1, 1);

    int st = 0, st_load = 2;
    for (int c = 0; c < nch; c++) {
        cp_wait<1>();
        __syncthreads();

        if (c + 2 < nch) {
            LOAD_CHUNK(c + 2, st_load);
            if (++st_load == NSTAGE) st_load = 0;
        } else {
            cp_commit();
        }

        const u32 sb = smb + st * STAGEB;
#pragma unroll
        for (int ks = 0; ks < 2; ks++) {
            u32 ah[2][4], al[2][4], bh[2][4], bl[2][4];
#pragma unroll
            for (int mi = 0; mi < 2; mi++) {
                u32 addr = sb + (a_row + mi * 16) * TPITCH + ks * 32 + a_col;
                ldm_x4(ah[mi], addr);
                if (ALIMBS == 2) ldm_x4(al[mi], addr + TILEA);
            }
#pragma unroll
            for (int nj2 = 0; nj2 < 2; nj2++) {
                u32 addr = sb + BOFF + (b_row + nj2 * 16) * TPITCH + ks * 32 + b_col;
                ldm_x4(bh[nj2], addr);
                if (BLIMBS == 2) ldm_x4(bl[nj2], addr + TILEA);
            }

#pragma unroll
            for (int mi = 0; mi < 2; mi++)
#pragma unroll
                for (int nj = 0; nj < 4; nj++)
                    mma16816(acc[mi][nj], ah[mi], &bh[nj >> 1][(nj & 1) * 2]);
            if (BLIMBS == 2) {
#pragma unroll
                for (int mi = 0; mi < 2; mi++)
#pragma unroll
                    for (int nj = 0; nj < 4; nj++)
                        mma16816(acc[mi][nj], ah[mi], &bl[nj >> 1][(nj & 1) * 2]);
            }
            if (ALIMBS == 2) {
#pragma unroll
                for (int mi = 0; mi < 2; mi++)
#pragma unroll
                    for (int nj = 0; nj < 4; nj++)
                        mma16816(acc[mi][nj], al[mi], &bh[nj >> 1][(nj & 1) * 2]);
            }
        }
        if (++st == NSTAGE) st = 0;
    }
#undef LOAD_CHUNK

    const int erow = m0 + warp_m * 32 + (lane >> 2);
    const int ecol0 = n0 + warp_n * 32 + (lane & 3) * 2;
#pragma unroll
    for (int mi = 0; mi < 2; mi++) {
#pragma unroll
        for (int nj = 0; nj < 4; nj++) {
            float v0 = acc[mi][nj][0], v1 = acc[mi][nj][1];
            float v2 = acc[mi][nj][2], v3 = acc[mi][nj][3];
            const int col = ecol0 + nj * 8;
            if (ADD_BIAS) {
                float b0 = bias[col], b1 = bias[col + 1];
                v0 += b0; v1 += b1; v2 += b0; v3 += b1;
            }
            const size_t r0 = (size_t)bz * sC + (size_t)(erow + mi * 16) * ldc + col;
            const size_t r1 = r0 + (size_t)8 * ldc;
            if (!WRITE_SPLIT) {
                *(float2*)(Cf + r0) = make_float2(v0, v1);
                *(float2*)(Cf + r1) = make_float2(v2, v3);
            } else {
                u32 h0 = packh(v1, v0);
                u32 l0 = packh(v1 - hi_h2f(h0), v0 - lo_h2f(h0));
                u32 h1 = packh(v3, v2);
                u32 l1 = packh(v3 - hi_h2f(h1), v2 - lo_h2f(h1));
                *(u32*)(Ch + r0) = h0; *(u32*)(Cl + r0) = l0;
                *(u32*)(Ch + r1) = h1; *(u32*)(Cl + r1) = l1;
            }
        }
    }
}

// =====================================================================
// Scores GEMM: CTA 128x256, 16 warps (32x64 warp tile), 2-limb A and B,
// 3 passes, fp32 out. MMA:LDSM ratio 4 (vs 3 in the 128x128 kernel).
// =====================================================================
#define TILEB256 (256 * TPITCH)
#define STAGE256 (2 * TILEA + 2 * TILEB256)   // 61440
#define SMEM256 (NSTAGE * STAGE256)           // 184320

__global__ void __launch_bounds__(512, 1) gemm_scores(
    const __half* __restrict__ Ah_, const __half* __restrict__ Al_,
    const __half* __restrict__ Bh_, const __half* __restrict__ Bl_,
    float* __restrict__ Cf,
    int K, int lda, int ldb, int ldc,
    long sA, long sB, long sC)
{
    constexpr int BOFF = 2 * TILEA;

    extern __shared__ char sm[];
    const u32 smb = smem_u32(sm);
    const int tid = threadIdx.x;
    const int wid = tid >> 5, lane = tid & 31;
    const int m0 = blockIdx.y * 128, n0 = blockIdx.x * 256;
    const int bz = blockIdx.z;

    const __half* Arh = Ah_ + (size_t)bz * sA + (size_t)m0 * lda;
    const __half* Arl = Al_ + (size_t)bz * sA + (size_t)m0 * lda;
    const __half* Brh = Bh_ + (size_t)bz * sB + (size_t)n0 * ldb;
    const __half* Brl = Bl_ + (size_t)bz * sB + (size_t)n0 * ldb;

    const int lrow = tid >> 2;            // 0..127
    const int lc = (tid & 3) * 16;

    // warp tile: warp_m in {0..3} (32 rows), warp_n in {0..3} (64 cols)
    const int warp_m = wid >> 2;
    const int warp_n = wid & 3;
    const int a_row = warp_m * 32 + (lane & 15);
    const int a_col = (lane >> 4) * 16;
    const int b_row = warp_n * 64 + ((lane >> 4) << 3) + (lane & 7);
    const int b_col = ((lane >> 3) & 1) * 16;

    float acc[2][8][4];
#pragma unroll
    for (int i = 0; i < 2; i++)
#pragma unroll
        for (int j = 0; j < 8; j++)
#pragma unroll
            for (int q = 0; q < 4; q++) acc[i][j][q] = 0.f;

    const int nch = K >> 5;

#define LOAD_CHUNK2(cidx, st)                                                      \
    do {                                                                           \
        const int kc_ = (cidx) << 5;                                               \
        const u32 sb_ = smb + (st) * STAGE256;                                     \
        cp16(sb_ + lrow * TPITCH + lc,                                             \
             (const char*)(Arh + (size_t)lrow * lda + kc_) + lc);                  \
        cp16(sb_ + TILEA + lrow * TPITCH + lc,                                     \
             (const char*)(Arl + (size_t)lrow * lda + kc_) + lc);                  \
        cp16(sb_ + BOFF + lrow * TPITCH + lc,                                      \
             (const char*)(Brh + (size_t)lrow * ldb + kc_) + lc);                  \
        cp16(sb_ + BOFF + (lrow + 128) * TPITCH + lc,                              \
             (const char*)(Brh + (size_t)(lrow + 128) * ldb + kc_) + lc);          \
        cp16(sb_ + BOFF + TILEB256 + lrow * TPITCH + lc,                           \
             (const char*)(Brl + (size_t)lrow * ldb + kc_) + lc);                  \
        cp16(sb_ + BOFF + TILEB256 + (lrow + 128) * TPITCH + lc,                   \
             (const char*)(Brl + (size_t)(lrow + 128) * ldb + kc_) + lc);          \
        cp_commit();                                                               \
    } while (0)

    LOAD_CHUNK2(0, 0);
    LOAD_CHUNK2(1, 1);

    int st = 0, st_load = 2;
    for (int c = 0; c < nch; c++) {
        cp_wait<1>();
        __syncthreads();

        if (c + 2 < nch) {
            LOAD_CHUNK2(c + 2, st_load);
            if (++st_load == NSTAGE) st_load = 0;
        } else {
            cp_commit();
        }

        const u32 sb = smb + st * STAGE256;
#pragma unroll
        for (int ks = 0; ks < 2; ks++) {
            // ---- pass 0: Ah * Bh ----
            u32 ah[2][4], bh[4][4];
#pragma unroll
            for (int mi = 0; mi < 2; mi++)
                ldm_x4(ah[mi], sb + (a_row + mi * 16) * TPITCH + ks * 32 + a_col);
#pragma unroll
            for (int nj2 = 0; nj2 < 4; nj2++)
                ldm_x4(bh[nj2], sb + BOFF + (b_row + nj2 * 16) * TPITCH + ks * 32 + b_col);
#pragma unroll
            for (int mi = 0; mi < 2; mi++)
#pragma unroll
                for (int nj = 0; nj < 8; nj++)
                    mma16816(acc[mi][nj], ah[mi], &bh[nj >> 1][(nj & 1) * 2]);

            {
                // ---- pass 1: Ah * Bl ----
                u32 bl[4][4];
#pragma unroll
                for (int nj2 = 0; nj2 < 4; nj2++)
                    ldm_x4(bl[nj2], sb + BOFF + TILEB256 + (b_row + nj2 * 16) * TPITCH + ks * 32 + b_col);
#pragma unroll
                for (int mi = 0; mi < 2; mi++)
#pragma unroll
                    for (int nj = 0; nj < 8; nj++)
                        mma16816(acc[mi][nj], ah[mi], &bl[nj >> 1][(nj & 1) * 2]);
            }
            {
                // ---- pass 2: Al * Bh ----
                u32 al[2][4];
#pragma unroll
                for (int mi = 0; mi < 2; mi++)
                    ldm_x4(al[mi], sb + TILEA + (a_row + mi * 16) * TPITCH + ks * 32 + a_col);
#pragma unroll
                for (int mi = 0; mi < 2; mi++)
#pragma unroll
                    for (int nj = 0; nj < 8; nj++)
                        mma16816(acc[mi][nj], al[mi], &bh[nj >> 1][(nj & 1) * 2]);
            }
        }
        if (++st == NSTAGE) st = 0;
    }
#undef LOAD_CHUNK2

    const int erow = m0 + warp_m * 32 + (lane >> 2);
    const int ecol0 = n0 + warp_n * 64 + (lane & 3) * 2;
#pragma unroll
    for (int mi = 0; mi < 2; mi++) {
#pragma unroll
        for (int nj = 0; nj < 8; nj++) {
            const int col = ecol0 + nj * 8;
            const size_t r0 = (size_t)bz * sC + (size_t)(erow + mi * 16) * ldc + col;
            const size_t r1 = r0 + (size_t)8 * ldc;
            *(float2*)(Cf + r0) = make_float2(acc[mi][nj][0], acc[mi][nj][1]);
            *(float2*)(Cf + r1) = make_float2(acc[mi][nj][2], acc[mi][nj][3]);
        }
    }
}

// =====================================================================
// fp32 -> (hi, lo) fp16 split converter (Q, W)
// =====================================================================
__global__ void __launch_bounds__(256) convert_split(
    const float* __restrict__ x, __half* __restrict__ h,
    __half* __restrict__ l, int n4)
{
    int i = blockIdx.x * 256 + threadIdx.x;
    if (i >= n4) return;
    float4 v = ((const float4*)x)[i];
    u32 h0 = packh(v.y, v.x);
    u32 h1 = packh(v.w, v.z);
    u32 l0 = packh(v.y - hi_h2f(h0), v.x - lo_h2f(h0));
    u32 l1 = packh(v.w - hi_h2f(h1), v.z - lo_h2f(h1));
    ((uint2*)h)[i] = make_uint2(h0, h1);
    ((uint2*)l)[i] = make_uint2(l0, l1);
}

// =====================================================================
// Fused attn_input prep: split (Ah, Al) K-major + transpose (Vt) in one read
// =====================================================================
__global__ void __launch_bounds__(256) fuse_attn(
    const float* __restrict__ x, __half* __restrict__ ah,
    __half* __restrict__ al, __half* __restrict__ vt)
{
    __shared__ float tile[32][33];
    const int tx = threadIdx.x & 31, ty = threadIdx.x >> 5;  // 32x8
    const int s0 = blockIdx.x * 32, d0 = blockIdx.y * 32, b = blockIdx.z;
    const float* src = x + (size_t)b * SN * DD;
#pragma unroll
    for (int j = 0; j < 4; j++) {
        int s = s0 + ty + j * 8;
        float v = src[(size_t)s * DD + d0 + tx];
        tile[ty + j * 8][tx] = v;
        __half h = __float2half_rn(v);
        size_t off = (size_t)b * SN * DD + (size_t)s * DD + d0 + tx;
        ah[off] = h;
        al[off] = __float2half_rn(v - __half2float(h));
    }
    __syncthreads();
#pragma unroll
    for (int j = 0; j < 4; j++) {
        int d = d0 + ty + j * 8;
        int s = s0 + tx;
        vt[(size_t)b * DD * SN + (size_t)d * SN + s] = __float2half_rn(tile[tx][ty + j * 8]);
    }
}

// =====================================================================
// Row softmax over S=2048 (fp32 in), writing fp16 P (hi limb only)
// =====================================================================
__global__ void __launch_bounds__(256) softmax_half(
    const float* __restrict__ P, __half* __restrict__ Ph)
{
    __shared__ float red[8];
    const int tid = threadIdx.x;
    const int lane = tid & 31, warp = tid >> 5;
    const float* row = P + (size_t)blockIdx.x * SN;

    float4 v0 = ((const float4*)row)[tid];
    float4 v1 = ((const float4*)row)[tid + 256];

    float m = fmaxf(fmaxf(fmaxf(v0.x, v0.y), fmaxf(v0.z, v0.w)),
                    fmaxf(fmaxf(v1.x, v1.y), fmaxf(v1.z, v1.w)));
#pragma unroll
    for (int o = 16; o > 0; o >>= 1) m = fmaxf(m, __shfl_xor_sync(0xffffffffu, m, o));
    if (lane == 0) red[warp] = m;
    __syncthreads();
    float mall = red[0];
#pragma unroll
    for (int k = 1; k < 8; k++) mall = fmaxf(mall, red[k]);
    __syncthreads();

    v0.x = __expf(v0.x - mall); v0.y = __expf(v0.y - mall);
    v0.z = __expf(v0.z - mall); v0.w = __expf(v0.w - mall);
    v1.x = __expf(v1.x - mall); v1.y = __expf(v1.y - mall);
    v1.z = __expf(v1.z - mall); v1.w = __expf(v1.w - mall);

    float s = (v0.x + v0.y) + (v0.z + v0.w) + (v1.x + v1.y) + (v1.z + v1.w);
#pragma unroll
    for (int o = 16; o > 0; o >>= 1) s += __shfl_xor_sync(0xffffffffu, s, o);
    if (lane == 0) red[warp] = s;
    __syncthreads();
    float sall = red[0];
#pragma unroll
    for (int k = 1; k < 8; k++) sall += red[k];
    float inv = 1.0f / sall;

    v0.x *= inv; v0.y *= inv; v0.z *= inv; v0.w *= inv;
    v1.x *= inv; v1.y *= inv; v1.z *= inv; v1.w *= inv;

    uint2* ph2 = (uint2*)(Ph + (size_t)blockIdx.x * SN);
    ph2[tid]       = make_uint2(packh(v0.y, v0.x), packh(v0.w, v0.z));
    ph2[tid + 256] = make_uint2(packh(v1.y, v1.x), packh(v1.w, v1.z));
}

// =====================================================================
// kernel_launch
// =====================================================================
extern "C" void kernel_launch(void* const* d_in, const int* in_sizes, int n_in,
                              void* d_out, int out_size) {
    const float* main_in = (const float*)d_in[0];
    const float* attn_in = (const float*)d_in[1];
    const float* W_f = (const float*)d_in[2];
    const float* b_f = (const float*)d_in[3];
    float* out = (float*)d_out;

    __half *Qh, *Ql, *Ah, *Al, *Vt, *Wh, *Wl, *Kh, *Kl, *Ph;
    float* P;
    cudaGetSymbolAddress((void**)&Qh, g_Qh);  cudaGetSymbolAddress((void**)&Ql, g_Ql);
    cudaGetSymbolAddress((void**)&Ah, g_Ah);  cudaGetSymbolAddress((void**)&Al, g_Al);
    cudaGetSymbolAddress((void**)&Vt, g_Vt);
    cudaGetSymbolAddress((void**)&Wh, g_Wh);  cudaGetSymbolAddress((void**)&Wl, g_Wl);
    cudaGetSymbolAddress((void**)&Kh, g_Kh);  cudaGetSymbolAddress((void**)&Kl, g_Kl);
    cudaGetSymbolAddress((void**)&Ph, g_Ph);
    cudaGetSymbolAddress((void**)&P, g_P);

    // 0) input prep (attn_input read once: split + transpose fused)
    {
        int n4q = (BB * TT * DD) / 4;
        convert_split<<<n4q / 256, 256>>>(main_in, Qh, Ql, n4q);
        int n4w = (DD * DD) / 4;
        convert_split<<<(n4w + 255) / 256, 256>>>(W_f, Wh, Wl, n4w);
        dim3 fg(SN / 32, DD / 32, BB);
        fuse_attn<<<fg, 256>>>(attn_in, Ah, Al, Vt);
    }

    constexpr int SMEM22 = NSTAGE * 4 * TILEA;  // 122880
    constexpr int SMEM11 = NSTAGE * 2 * TILEA;  // 61440
    cudaFuncSetAttribute(gemm_mma<2, 2, true, true>,
                         cudaFuncAttributeMaxDynamicSharedMemorySize, SMEM22);
    cudaFuncSetAttribute(gemm_scores,
                         cudaFuncAttributeMaxDynamicSharedMemorySize, SMEM256);
    cudaFuncSetAttribute(gemm_mma<1, 1, false, false>,
                         cudaFuncAttributeMaxDynamicSharedMemorySize, SMEM11);

    // 1) keys = attn @ W^T + b -> split fp16 (Kh + Kl). 3 passes.
    {
        dim3 grid(DD / 128, (BB * SN) / 128, 1);
        gemm_mma<2, 2, true, true><<<grid, 512, SMEM22>>>(
            Ah, Al, Wh, Wl, b_f, nullptr, Kh, Kl,
            DD, DD, DD, DD, 0, 0, 0);
    }

    // 2) scores = (Qh+Ql) @ (Kh+Kl)^T -> fp32 P. 3 passes, CTA 128x256.
    {
        dim3 grid(SN / 256, TT / 128, BB);   // (8, 16, 8) = 1024 CTAs
        gemm_scores<<<grid, 512, SMEM256>>>(
            Qh, Ql, Kh, Kl, P,
            DD, DD, DD, SN,
            (long)TT * DD, (long)SN * DD, (long)TT * SN);
    }

    // 3) softmax -> fp16 Ph
    softmax_half<<<BB * TT, 256>>>(P, Ph);

    // 4) out = Ph @ Vt. single pass.
    {
        dim3 grid(DD / 128, TT / 128, BB);
        gemm_mma<1, 1, false, false><<<grid, 512, SMEM11>>>(
            Ph, nullptr, Vt, nullptr, nullptr, out, nullptr, nullptr,
            SN, SN, SN, DD,
            (long)TT * SN, (long)DD * SN, (long)TT * DD);
    }
}

// round 15
// speedup vs baseline: 1.4649x; 1.0637x over previous
#include <cuda_runtime.h>
#include <cuda_fp16.h>
#include <cstdint>

// Problem constants: B=8, T=2048, S=2048, D=512
#define BB 8
#define TT 2048
#define SN 2048
#define DD 512

typedef uint32_t u32;
typedef uint64_t u64;

// ----------------- device scratch (allocation-free rules) -----------------
__device__ __half g_Qh[(size_t)BB * TT * DD];
__device__ __half g_Ql[(size_t)BB * TT * DD];
__device__ __half g_Ah[(size_t)BB * SN * DD];   // attn_input split (K-major)
__device__ __half g_Al[(size_t)BB * SN * DD];
__device__ __half g_Vt[(size_t)BB * DD * SN];   // attn_input transposed [B][D][S], hi limb
__device__ __half g_Wh[(size_t)DD * DD];
__device__ __half g_Wl[(size_t)DD * DD];
__device__ __half g_Kh[(size_t)BB * SN * DD];
__device__ __half g_Kl[(size_t)BB * SN * DD];
__device__ float g_P[(size_t)BB * TT * SN];     // 128 MB raw scores
__device__ __half g_Ph[(size_t)BB * TT * SN];   // 64 MB softmax probs

// ----------------- helpers -----------------
__device__ __forceinline__ u32 smem_u32(const void* p) {
    u32 a;
    asm("{ .reg .u64 t; cvta.to.shared.u64 t, %1; cvt.u32.u64 %0, t; }" : "=r"(a) : "l"(p));
    return a;
}
// pack two fp32 -> half2 word; first arg = high half, second = low half
__device__ __forceinline__ u32 packh(float hi_elem, float lo_elem) {
    __half2 h = __floats2half2_rn(lo_elem, hi_elem);
    return *(u32*)&h;
}
__device__ __forceinline__ float lo_h2f(u32 p) {
    __half2 h = *(__half2*)&p;
    return __half2float(__low2half(h));
}
__device__ __forceinline__ float hi_h2f(u32 p) {
    __half2 h = *(__half2*)&p;
    return __half2float(__high2half(h));
}

__device__ __forceinline__ void cp16(u32 dst, const void* src) {
    asm volatile("cp.async.cg.shared.global [%0], [%1], 16;" :: "r"(dst), "l"(src));
}
__device__ __forceinline__ void cp_commit() {
    asm volatile("cp.async.commit_group;" ::: "memory");
}
template <int N>
__device__ __forceinline__ void cp_wait() {
    asm volatile("cp.async.wait_group %0;" :: "n"(N) : "memory");
}

__device__ __forceinline__ void ldm_x4(u32* r, u32 addr) {
    asm volatile("ldmatrix.sync.aligned.m8n8.x4.shared.b16 {%0,%1,%2,%3}, [%4];"
                 : "=r"(r[0]), "=r"(r[1]), "=r"(r[2]), "=r"(r[3]) : "r"(addr));
}
__device__ __forceinline__ void mma16816(float* d, const u32* a, const u32* b) {
    asm volatile(
        "mma.sync.aligned.m16n8k16.row.col.f32.f16.f16.f32 "
        "{%0,%1,%2,%3}, {%4,%5,%6,%7}, {%8,%9}, {%0,%1,%2,%3};"
        : "+f"(d[0]), "+f"(d[1]), "+f"(d[2]), "+f"(d[3])
        : "r"(a[0]), "r"(a[1]), "r"(a[2]), "r"(a[3]), "r"(b[0]), "r"(b[1]));
}

// ----------------- GEMM smem layout -----------------
// Tiles: rows x 32 fp16 (64B data), row pitch 80B (conflict-free ldmatrix).
#define TPITCH 80
#define TILEA (128 * TPITCH)     // A tile: 128 rows
#define TILEB (256 * TPITCH)     // B tile: 256 rows
#define NSTAGE 3

// =====================================================================
// NT split-fp16 GEMM, CTA 128x256, 16 warps (32x64 warp tile).
//   C[m][n] = sum_k A[m][k]*B(n,k) (+bias[n])
//   ALIMBS/BLIMBS in {1,2}. Passes (pass-major): hh [, Ah*Bl] [, Al*Bh].
//   WRITE_SPLIT: write hi/lo fp16 limb pair instead of fp32.
//   K-chunk 32, 3-stage cp.async. MMA:LDSM ratio 4 (2,2) / 2.67 (1,1).
// =====================================================================
template <int ALIMBS, int BLIMBS, bool WRITE_SPLIT, bool ADD_BIAS>
__global__ void __launch_bounds__(512, 1) gemm_mma256(
    const __half* __restrict__ Ah_, const __half* __restrict__ Al_,
    const __half* __restrict__ Bh_, const __half* __restrict__ Bl_,
    const float* __restrict__ bias,
    float* __restrict__ Cf, __half* __restrict__ Ch, __half* __restrict__ Cl,
    int K, int lda, int ldb, int ldc,
    long sA, long sB, long sC)
{
    constexpr int STAGEB = ALIMBS * TILEA + BLIMBS * TILEB;
    constexpr int BOFF = ALIMBS * TILEA;

    extern __shared__ char sm[];
    const u32 smb = smem_u32(sm);
    const int tid = threadIdx.x;
    const int wid = tid >> 5, lane = tid & 31;
    const int m0 = blockIdx.y * 128, n0 = blockIdx.x * 256;
    const int bz = blockIdx.z;

    const __half* Arh = Ah_ + (size_t)bz * sA + (size_t)m0 * lda;
    const __half* Arl = (ALIMBS == 2) ? (Al_ + (size_t)bz * sA + (size_t)m0 * lda) : nullptr;
    const __half* Brh = Bh_ + (size_t)bz * sB + (size_t)n0 * ldb;
    const __half* Brl = (BLIMBS == 2) ? (Bl_ + (size_t)bz * sB + (size_t)n0 * ldb) : nullptr;

    // loader: 512 threads. A tile: 1 x 16B per thread (row lrow).
    // B tile: 2 x 16B per thread (rows lrow, lrow+128).
    const int lrow = tid >> 2;            // 0..127
    const int lc = (tid & 3) * 16;

    // warp tile: warp_m in {0..3} (32 rows), warp_n in {0..3} (64 cols)
    const int warp_m = wid >> 2;
    const int warp_n = wid & 3;
    const int a_row = warp_m * 32 + (lane & 15);
    const int a_col = (lane >> 4) * 16;
    const int b_row = warp_n * 64 + ((lane >> 4) << 3) + (lane & 7);
    const int b_col = ((lane >> 3) & 1) * 16;

    float acc[2][8][4];
#pragma unroll
    for (int i = 0; i < 2; i++)
#pragma unroll
        for (int j = 0; j < 8; j++)
#pragma unroll
            for (int q = 0; q < 4; q++) acc[i][j][q] = 0.f;

    const int nch = K >> 5;

#define LOAD_CHUNK(cidx, st)                                                       \
    do {                                                                           \
        const int kc_ = (cidx) << 5;                                               \
        const u32 sb_ = smb + (st) * STAGEB;                                       \
        cp16(sb_ + lrow * TPITCH + lc,                                             \
             (const char*)(Arh + (size_t)lrow * lda + kc_) + lc);                  \
        if (ALIMBS == 2)                                                           \
            cp16(sb_ + TILEA + lrow * TPITCH + lc,                                 \
                 (const char*)(Arl + (size_t)lrow * lda + kc_) + lc);              \
        cp16(sb_ + BOFF + lrow * TPITCH + lc,                                      \
             (const char*)(Brh + (size_t)lrow * ldb + kc_) + lc);                  \
        cp16(sb_ + BOFF + (lrow + 128) * TPITCH + lc,                              \
             (const char*)(Brh + (size_t)(lrow + 128) * ldb + kc_) + lc);          \
        if (BLIMBS == 2) {                                                         \
            cp16(sb_ + BOFF + TILEB + lrow * TPITCH + lc,                          \
                 (const char*)(Brl + (size_t)lrow * ldb + kc_) + lc);              \
            cp16(sb_ + BOFF + TILEB + (lrow + 128) * TPITCH + lc,                  \
                 (const char*)(Brl + (size_t)(lrow + 128) * ldb + kc_) + lc);      \
        }                                                                          \
        cp_commit();                                                               \
    } while (0)

    LOAD_CHUNK(0, 0);
    LOAD_CHUNK(1, 1);

    int st = 0, st_load = 2;
    for (int c = 0; c < nch; c++) {
        cp_wait<1>();
        __syncthreads();

        if (c + 2 < nch) {
            LOAD_CHUNK(c + 2, st_load);
            if (++st_load == NSTAGE) st_load = 0;
        } else {
            cp_commit();
        }

        const u32 sb = smb + st * STAGEB;
#pragma unroll
        for (int ks = 0; ks < 2; ks++) {
            // ---- pass 0: Ah * Bh ----
            u32 ah[2][4], bh[4][4];
#pragma unroll
            for (int mi = 0; mi < 2; mi++)
                ldm_x4(ah[mi], sb + (a_row + mi * 16) * TPITCH + ks * 32 + a_col);
#pragma unroll
            for (int nj2 = 0; nj2 < 4; nj2++)
                ldm_x4(bh[nj2], sb + BOFF + (b_row + nj2 * 16) * TPITCH + ks * 32 + b_col);
#pragma unroll
            for (int mi = 0; mi < 2; mi++)
#pragma unroll
                for (int nj = 0; nj < 8; nj++)
                    mma16816(acc[mi][nj], ah[mi], &bh[nj >> 1][(nj & 1) * 2]);

            if (BLIMBS == 2) {
                // ---- pass 1: Ah * Bl ----
                u32 bl[4][4];
#pragma unroll
                for (int nj2 = 0; nj2 < 4; nj2++)
                    ldm_x4(bl[nj2], sb + BOFF + TILEB + (b_row + nj2 * 16) * TPITCH + ks * 32 + b_col);
#pragma unroll
                for (int mi = 0; mi < 2; mi++)
#pragma unroll
                    for (int nj = 0; nj < 8; nj++)
                        mma16816(acc[mi][nj], ah[mi], &bl[nj >> 1][(nj & 1) * 2]);
            }
            if (ALIMBS == 2) {
                // ---- pass 2: Al * Bh ----
                u32 al[2][4];
#pragma unroll
                for (int mi = 0; mi < 2; mi++)
                    ldm_x4(al[mi], sb + TILEA + (a_row + mi * 16) * TPITCH + ks * 32 + a_col);
#pragma unroll
                for (int mi = 0; mi < 2; mi++)
#pragma unroll
                    for (int nj = 0; nj < 8; nj++)
                        mma16816(acc[mi][nj], al[mi], &bh[nj >> 1][(nj & 1) * 2]);
            }
        }
        if (++st == NSTAGE) st = 0;
    }
#undef LOAD_CHUNK

    // ---- epilogue ----
    const int erow = m0 + warp_m * 32 + (lane >> 2);
    const int ecol0 = n0 + warp_n * 64 + (lane & 3) * 2;
#pragma unroll
    for (int mi = 0; mi < 2; mi++) {
#pragma unroll
        for (int nj = 0; nj < 8; nj++) {
            float v0 = acc[mi][nj][0], v1 = acc[mi][nj][1];
            float v2 = acc[mi][nj][2], v3 = acc[mi][nj][3];
            const int col = ecol0 + nj * 8;
            if (ADD_BIAS) {
                float b0 = bias[col], b1 = bias[col + 1];
                v0 += b0; v1 += b1; v2 += b0; v3 += b1;
            }
            const size_t r0 = (size_t)bz * sC + (size_t)(erow + mi * 16) * ldc + col;
            const size_t r1 = r0 + (size_t)8 * ldc;
            if (!WRITE_SPLIT) {
                *(float2*)(Cf + r0) = make_float2(v0, v1);
                *(float2*)(Cf + r1) = make_float2(v2, v3);
            } else {
                u32 h0 = packh(v1, v0);
                u32 l0 = packh(v1 - hi_h2f(h0), v0 - lo_h2f(h0));
                u32 h1 = packh(v3, v2);
                u32 l1 = packh(v3 - hi_h2f(h1), v2 - lo_h2f(h1));
                *(u32*)(Ch + r0) = h0; *(u32*)(Cl + r0) = l0;
                *(u32*)(Ch + r1) = h1; *(u32*)(Cl + r1) = l1;
            }
        }
    }
}

// =====================================================================
// fp32 -> (hi, lo) fp16 split converter (Q, W)
// =====================================================================
__global__ void __launch_bounds__(256) convert_split(
    const float* __restrict__ x, __half* __restrict__ h,
    __half* __restrict__ l, int n4)
{
    int i = blockIdx.x * 256 + threadIdx.x;
    if (i >= n4) return;
    float4 v = ((const float4*)x)[i];
    u32 h0 = packh(v.y, v.x);
    u32 h1 = packh(v.w, v.z);
    u32 l0 = packh(v.y - hi_h2f(h0), v.x - lo_h2f(h0));
    u32 l1 = packh(v.w - hi_h2f(h1), v.z - lo_h2f(h1));
    ((uint2*)h)[i] = make_uint2(h0, h1);
    ((uint2*)l)[i] = make_uint2(l0, l1);
}

// =====================================================================
// Fused attn_input prep: split (Ah, Al) K-major + transpose (Vt) in one read
// =====================================================================
__global__ void __launch_bounds__(256) fuse_attn(
    const float* __restrict__ x, __half* __restrict__ ah,
    __half* __restrict__ al, __half* __restrict__ vt)
{
    __shared__ float tile[32][33];
    const int tx = threadIdx.x & 31, ty = threadIdx.x >> 5;  // 32x8
    const int s0 = blockIdx.x * 32, d0 = blockIdx.y * 32, b = blockIdx.z;
    const float* src = x + (size_t)b * SN * DD;
#pragma unroll
    for (int j = 0; j < 4; j++) {
        int s = s0 + ty + j * 8;
        float v = src[(size_t)s * DD + d0 + tx];
        tile[ty + j * 8][tx] = v;
        __half h = __float2half_rn(v);
        size_t off = (size_t)b * SN * DD + (size_t)s * DD + d0 + tx;
        ah[off] = h;
        al[off] = __float2half_rn(v - __half2float(h));
    }
    __syncthreads();
#pragma unroll
    for (int j = 0; j < 4; j++) {
        int d = d0 + ty + j * 8;
        int s = s0 + tx;
        vt[(size_t)b * DD * SN + (size_t)d * SN + s] = __float2half_rn(tile[tx][ty + j * 8]);
    }
}

// =====================================================================
// Row softmax over S=2048 (fp32 in), writing fp16 P (hi limb only)
// =====================================================================
__global__ void __launch_bounds__(256) softmax_half(
    const float* __restrict__ P, __half* __restrict__ Ph)
{
    __shared__ float red[8];
    const int tid = threadIdx.x;
    const int lane = tid & 31, warp = tid >> 5;
    const float* row = P + (size_t)blockIdx.x * SN;

    float4 v0 = ((const float4*)row)[tid];
    float4 v1 = ((const float4*)row)[tid + 256];

    float m = fmaxf(fmaxf(fmaxf(v0.x, v0.y), fmaxf(v0.z, v0.w)),
                    fmaxf(fmaxf(v1.x, v1.y), fmaxf(v1.z, v1.w)));
#pragma unroll
    for (int o = 16; o > 0; o >>= 1) m = fmaxf(m, __shfl_xor_sync(0xffffffffu, m, o));
    if (lane == 0) red[warp] = m;
    __syncthreads();
    float mall = red[0];
#pragma unroll
    for (int k = 1; k < 8; k++) mall = fmaxf(mall, red[k]);
    __syncthreads();

    v0.x = __expf(v0.x - mall); v0.y = __expf(v0.y - mall);
    v0.z = __expf(v0.z - mall); v0.w = __expf(v0.w - mall);
    v1.x = __expf(v1.x - mall); v1.y = __expf(v1.y - mall);
    v1.z = __expf(v1.z - mall); v1.w = __expf(v1.w - mall);

    float s = (v0.x + v0.y) + (v0.z + v0.w) + (v1.x + v1.y) + (v1.z + v1.w);
#pragma unroll
    for (int o = 16; o > 0; o >>= 1) s += __shfl_xor_sync(0xffffffffu, s, o);
    if (lane == 0) red[warp] = s;
    __syncthreads();
    float sall = red[0];
#pragma unroll
    for (int k = 1; k < 8; k++) sall += red[k];
    float inv = 1.0f / sall;

    v0.x *= inv; v0.y *= inv; v0.z *= inv; v0.w *= inv;
    v1.x *= inv; v1.y *= inv; v1.z *= inv; v1.w *= inv;

    uint2* ph2 = (uint2*)(Ph + (size_t)blockIdx.x * SN);
    ph2[tid]       = make_uint2(packh(v0.y, v0.x), packh(v0.w, v0.z));
    ph2[tid + 256] = make_uint2(packh(v1.y, v1.x), packh(v1.w, v1.z));
}

// =====================================================================
// kernel_launch
// =====================================================================
extern "C" void kernel_launch(void* const* d_in, const int* in_sizes, int n_in,
                              void* d_out, int out_size) {
    const float* main_in = (const float*)d_in[0];
    const float* attn_in = (const float*)d_in[1];
    const float* W_f = (const float*)d_in[2];
    const float* b_f = (const float*)d_in[3];
    float* out = (float*)d_out;

    __half *Qh, *Ql, *Ah, *Al, *Vt, *Wh, *Wl, *Kh, *Kl, *Ph;
    float* P;
    cudaGetSymbolAddress((void**)&Qh, g_Qh);  cudaGetSymbolAddress((void**)&Ql, g_Ql);
    cudaGetSymbolAddress((void**)&Ah, g_Ah);  cudaGetSymbolAddress((void**)&Al, g_Al);
    cudaGetSymbolAddress((void**)&Vt, g_Vt);
    cudaGetSymbolAddress((void**)&Wh, g_Wh);  cudaGetSymbolAddress((void**)&Wl, g_Wl);
    cudaGetSymbolAddress((void**)&Kh, g_Kh);  cudaGetSymbolAddress((void**)&Kl, g_Kl);
    cudaGetSymbolAddress((void**)&Ph, g_Ph);
    cudaGetSymbolAddress((void**)&P, g_P);

    // 0) input prep (attn_input read once: split + transpose fused)
    {
        int n4q = (BB * TT * DD) / 4;
        convert_split<<<n4q / 256, 256>>>(main_in, Qh, Ql, n4q);
        int n4w = (DD * DD) / 4;
        convert_split<<<(n4w + 255) / 256, 256>>>(W_f, Wh, Wl, n4w);
        dim3 fg(SN / 32, DD / 32, BB);
        fuse_attn<<<fg, 256>>>(attn_in, Ah, Al, Vt);
    }

    constexpr int SMEM22 = NSTAGE * (2 * TILEA + 2 * TILEB);  // 184320
    constexpr int SMEM11 = NSTAGE * (TILEA + TILEB);          // 92160
    cudaFuncSetAttribute(gemm_mma256<2, 2, true, true>,
                         cudaFuncAttributeMaxDynamicSharedMemorySize, SMEM22);
    cudaFuncSetAttribute(gemm_mma256<2, 2, false, false>,
                         cudaFuncAttributeMaxDynamicSharedMemorySize, SMEM22);
    cudaFuncSetAttribute(gemm_mma256<1, 1, false, false>,
                         cudaFuncAttributeMaxDynamicSharedMemorySize, SMEM11);

    // 1) keys = attn @ W^T + b -> split fp16 (Kh + Kl). 3 passes, CTA 128x256.
    {
        dim3 grid(DD / 256, (BB * SN) / 128, 1);   // (2, 128, 1)
        gemm_mma256<2, 2, true, true><<<grid, 512, SMEM22>>>(
            Ah, Al, Wh, Wl, b_f, nullptr, Kh, Kl,
            DD, DD, DD, DD, 0, 0, 0);
    }

    // 2) scores = (Qh+Ql) @ (Kh+Kl)^T -> fp32 P. 3 passes, CTA 128x256.
    {
        dim3 grid(SN / 256, TT / 128, BB);          // (8, 16, 8)
        gemm_mma256<2, 2, false, false><<<grid, 512, SMEM22>>>(
            Qh, Ql, Kh, Kl, nullptr, P, nullptr, nullptr,
            DD, DD, DD, SN,
            (long)TT * DD, (long)SN * DD, (long)TT * SN);
    }

    // 3) softmax -> fp16 Ph
    softmax_half<<<BB * TT, 256>>>(P, Ph);

    // 4) out = Ph @ Vt. single pass, CTA 128x256.
    {
        dim3 grid(DD / 256, TT / 128, BB);          // (2, 16, 8)
        gemm_mma256<1, 1, false, false><<<grid, 512, SMEM11>>>(
            Ph, nullptr, Vt, nullptr, nullptr, out, nullptr, nullptr,
            SN, SN, SN, DD,
            (long)TT * SN, (long)DD * SN, (long)TT * DD);
    }
}